// round 16
// baseline (speedup 1.0000x reference)
#include <cuda_runtime.h>
#include <cuda_bf16.h>
#include <cstdint>
#include <math.h>

#define BB    64
#define TT    512
#define DD    256
#define HH    512
#define TTBB  (TT * BB)     // 32768
#define NCTA  128
#define NGRP  64
#define NTH   256
#define RTH   512           // rec kernel threads (16 warps)

// ---------------------------------------------------------------------------
// Global scratch
// ---------------------------------------------------------------------------
__device__ __nv_bfloat16 g_xhi[DD * TTBB];      // x planes [d][t][b]
__device__ __nv_bfloat16 g_xlo[DD * TTBB];
__device__ __nv_bfloat16 g_o0hi[HH * TTBB];     // layer0 out planes [h][t][b]
__device__ __nv_bfloat16 g_o0lo[HH * TTBB];
__device__ __nv_bfloat16 g_hhi[2 * HH * BB];    // h planes [buf][h][b]
__device__ __nv_bfloat16 g_hlo[2 * HH * BB];
__device__ __nv_bfloat16 g_wih0hi[4 * HH * DD];
__device__ __nv_bfloat16 g_wih0lo[4 * HH * DD];
__device__ __nv_bfloat16 g_wih1hi[4 * HH * HH];
__device__ __nv_bfloat16 g_wih1lo[4 * HH * HH];
__device__ float g_xg0[(size_t)4 * HH * TTBB];
__device__ float g_xg1[(size_t)4 * HH * TTBB];
__device__ unsigned g_bar_count[2];
__device__ unsigned g_bar_epoch[2];

// ---------------------------------------------------------------------------
// Helpers
// ---------------------------------------------------------------------------
__device__ __forceinline__ void ldsm_x4(uint32_t (&r)[4], uint32_t addr) {
    asm volatile("ldmatrix.sync.aligned.m8n8.x4.shared.b16 {%0,%1,%2,%3}, [%4];\n"
                 : "=r"(r[0]), "=r"(r[1]), "=r"(r[2]), "=r"(r[3]) : "r"(addr));
}
__device__ __forceinline__ void ldsm_x2t(uint32_t (&r)[2], uint32_t addr) {
    asm volatile("ldmatrix.sync.aligned.m8n8.x2.trans.shared.b16 {%0,%1}, [%2];\n"
                 : "=r"(r[0]), "=r"(r[1]) : "r"(addr));
}
__device__ __forceinline__ void mma_bf16(float (&d)[4], const uint32_t (&a)[4],
                                         const uint32_t (&b)[2]) {
    asm volatile("mma.sync.aligned.m16n8k16.row.col.f32.bf16.bf16.f32 "
                 "{%0,%1,%2,%3}, {%4,%5,%6,%7}, {%8,%9}, {%0,%1,%2,%3};\n"
                 : "+f"(d[0]), "+f"(d[1]), "+f"(d[2]), "+f"(d[3])
                 : "r"(a[0]), "r"(a[1]), "r"(a[2]), "r"(a[3]),
                   "r"(b[0]), "r"(b[1]));
}
__device__ __forceinline__ void split_bf16(float v, __nv_bfloat16& hi, __nv_bfloat16& lo) {
    hi = __float2bfloat16_rn(v);
    lo = __float2bfloat16_rn(v - __bfloat162float(hi));
}
__device__ __forceinline__ void cp_async16(uint32_t dst, const void* src) {
    asm volatile("cp.async.cg.shared.global [%0], [%1], 16;\n" :: "r"(dst), "l"(src));
}
__device__ __forceinline__ void cp_commit() {
    asm volatile("cp.async.commit_group;\n");
}
template <int N>
__device__ __forceinline__ void cp_wait() {
    asm volatile("cp.async.wait_group %0;\n" :: "n"(N));
}

// ---------------------------------------------------------------------------
// MUFU-free activation math
// ---------------------------------------------------------------------------
__device__ __forceinline__ float fast_exp(float x) {
    float z = x * 1.4426950408889634f;
    float nf = rintf(z);
    float f = z - nf;
    float p = 1.535336188319500e-4f;
    p = fmaf(p, f, 1.339887440266574e-3f);
    p = fmaf(p, f, 9.618437357674640e-3f);
    p = fmaf(p, f, 5.550332471162809e-2f);
    p = fmaf(p, f, 2.402264791363012e-1f);
    p = fmaf(p, f, 6.931472028550421e-1f);
    p = fmaf(p, f, 1.0f);
    int n = (int)nf;
    return p * __int_as_float((n + 127) << 23);
}
__device__ __forceinline__ float fast_rcp(float x) {
    float y = __int_as_float(0x7EF311C3 - __float_as_int(x));
    y = y * (2.0f - x * y);
    y = y * (2.0f - x * y);
    y = y * (2.0f - x * y);
    return y;
}
__device__ __forceinline__ float fast_sigmoid(float x) {
    x = fminf(30.0f, fmaxf(-30.0f, x));
    return fast_rcp(1.0f + fast_exp(-x));
}
__device__ __forceinline__ float fast_tanh(float x) {
    x = fminf(15.0f, fmaxf(-15.0f, x));
    float e = fast_exp(2.0f * x);
    return (e - 1.0f) * fast_rcp(e + 1.0f);
}

// ---------------------------------------------------------------------------
// Flat grid barrier (64 CTAs per group, all co-resident; proven)
// ---------------------------------------------------------------------------
__device__ __forceinline__ void grid_barrier(int tid, int grp, unsigned& target) {
    __threadfence();
    __syncthreads();
    target += 1;
    if (tid == 0) {
        unsigned old = atomicAdd(&g_bar_count[grp], 1u);
        if (old == NGRP - 1) {
            atomicExch(&g_bar_count[grp], 0u);
            __threadfence();
            atomicAdd(&g_bar_epoch[grp], 1u);
        } else {
            while ((int)(*(volatile unsigned*)&g_bar_epoch[grp] - target) < 0) {
                __nanosleep(32);
            }
            __threadfence();
        }
    }
    __syncthreads();
}

// ---------------------------------------------------------------------------
// Split fp32 weights into bf16 hi/lo planes
// ---------------------------------------------------------------------------
__global__ void split_w_kernel(const float* __restrict__ W,
                               __nv_bfloat16* __restrict__ hi,
                               __nv_bfloat16* __restrict__ lo, int n) {
    for (int i = blockIdx.x * blockDim.x + threadIdx.x; i < n; i += gridDim.x * blockDim.x) {
        __nv_bfloat16 h, l;
        split_bf16(W[i], h, l);
        hi[i] = h;
        lo[i] = l;
    }
}

// ---------------------------------------------------------------------------
// Transpose + split x: [b][t][d] -> planes [d][t][b]
// ---------------------------------------------------------------------------
__global__ void transpose_x_kernel(const float* __restrict__ x) {
    extern __shared__ float sm[];
    const int t = blockIdx.x;
    const int tid = threadIdx.x;
    for (int i = tid; i < BB * DD; i += NTH) {
        int b = i >> 8;
        int d = i & 255;
        sm[d * 65 + b] = x[(size_t)b * (TT * DD) + (size_t)t * DD + d];
    }
    __syncthreads();
    for (int i = tid; i < DD * BB; i += NTH) {
        int d = i >> 6;
        int b = i & 63;
        float v = sm[d * 65 + b];
        __nv_bfloat16 hi, lo;
        split_bf16(v, hi, lo);
        const size_t idx = (size_t)d * TTBB + t * BB + b;
        g_xhi[idx] = hi;
        g_xlo[idx] = lo;
    }
}

// ---------------------------------------------------------------------------
// Bulk GEMM (unchanged, proven: tensor 62%)
// ---------------------------------------------------------------------------
template <int K>
__global__ __launch_bounds__(NTH)
void gemm_xg_kernel(const __nv_bfloat16* __restrict__ Whi,
                    const __nv_bfloat16* __restrict__ Wlo,
                    const __nv_bfloat16* __restrict__ Xhi,
                    const __nv_bfloat16* __restrict__ Xlo,
                    float* __restrict__ C) {
    constexpr int NKC = K / 32;
    extern __shared__ char sm_raw[];
    const uint32_t sbase = (uint32_t)__cvta_generic_to_shared(sm_raw);

    const int tid  = threadIdx.x;
    const int lane = tid & 31;
    const int w    = tid >> 5;
    const int wj   = w >> 2;
    const int wn0g = (w & 3) * 4;
    const int j0   = blockIdx.y * 128;
    const int n0   = blockIdx.x * 128;

    auto stage = [&](int kc, int buf) {
        const uint32_t bb = sbase + buf * 32768;
        #pragma unroll
        for (int q = 0; q < 4; ++q) {
            int idx = tid + q * 256;
            int p   = idx >> 9;
            int rem = idx & 511;
            int jl  = rem >> 2;
            int kh  = (rem >> 1) & 1;
            int g   = rem & 1;
            const __nv_bfloat16* src = (p ? Wlo : Whi)
                + (size_t)(j0 + jl) * K + kc * 32 + kh * 16 + g * 8;
            uint32_t dst = bb + p * 8192
                + (((jl >> 4) * 2 + kh) * 512)
                + (jl & 15) * 32
                + ((((unsigned)g) ^ (((unsigned)jl >> 2) & 1u)) << 4);
            cp_async16(dst, src);
        }
        #pragma unroll
        for (int q = 0; q < 4; ++q) {
            int idx = tid + q * 256;
            int p   = idx >> 9;
            int rem = idx & 511;
            int k   = rem >> 4;
            int g   = rem & 15;
            const __nv_bfloat16* src = (p ? Xlo : Xhi)
                + (size_t)(kc * 32 + k) * TTBB + n0 + g * 8;
            uint32_t dst = bb + 16384 + p * 8192 + k * 256
                + ((((unsigned)g) ^ ((unsigned)k & 7u)) << 4);
            cp_async16(dst, src);
        }
        cp_commit();
    };

    const uint32_t a_off = (uint32_t)((lane & 15) * 32
        + ((((unsigned)lane >> 4) ^ ((((unsigned)lane & 15) >> 2) & 1u)) << 4));

    float acc[4][4][4];
    #pragma unroll
    for (int mj = 0; mj < 4; ++mj)
        #pragma unroll
        for (int nj = 0; nj < 4; ++nj)
            #pragma unroll
            for (int q = 0; q < 4; ++q) acc[mj][nj][q] = 0.0f;

    stage(0, 0);
    for (int kc = 0; kc < NKC; ++kc) {
        if (kc + 1 < NKC) {
            stage(kc + 1, (kc + 1) & 1);
            cp_wait<1>();
        } else {
            cp_wait<0>();
        }
        __syncthreads();

        const uint32_t bb = sbase + (kc & 1) * 32768;
        const uint32_t Ahi_b = bb, Alo_b = bb + 8192;
        const uint32_t Bhi_b = bb + 16384, Blo_b = bb + 24576;

        #pragma unroll
        for (int kt = 0; kt < 2; ++kt) {
            uint32_t ahi[4][4], alo[4][4], bhi[4][2], blo[4][2];
            #pragma unroll
            for (int mj = 0; mj < 4; ++mj) {
                const uint32_t ta = (uint32_t)(((wj * 4 + mj) * 2 + kt) * 512) + a_off;
                ldsm_x4(ahi[mj], Ahi_b + ta);
                ldsm_x4(alo[mj], Alo_b + ta);
            }
            const uint32_t krow = (uint32_t)(kt * 16 + (lane & 15));
            #pragma unroll
            for (int nj = 0; nj < 4; ++nj) {
                const uint32_t go = (((uint32_t)(wn0g + nj)) ^ (krow & 7u)) << 4;
                ldsm_x2t(bhi[nj], Bhi_b + krow * 256 + go);
                ldsm_x2t(blo[nj], Blo_b + krow * 256 + go);
            }
            #pragma unroll
            for (int mj = 0; mj < 4; ++mj)
                #pragma unroll
                for (int nj = 0; nj < 4; ++nj) {
                    mma_bf16(acc[mj][nj], ahi[mj], bhi[nj]);
                    mma_bf16(acc[mj][nj], ahi[mj], blo[nj]);
                    mma_bf16(acc[mj][nj], alo[mj], bhi[nj]);
                }
        }
        __syncthreads();
    }

    #pragma unroll
    for (int mj = 0; mj < 4; ++mj) {
        const int jr = j0 + wj * 64 + mj * 16 + (lane >> 2);
        #pragma unroll
        for (int nj = 0; nj < 4; ++nj) {
            const int nc = n0 + (w & 3) * 32 + nj * 8 + (lane & 3) * 2;
            float2 v0 = make_float2(acc[mj][nj][0], acc[mj][nj][1]);
            float2 v1 = make_float2(acc[mj][nj][2], acc[mj][nj][3]);
            *(float2*)(C + (size_t)jr * TTBB + nc)       = v0;
            *(float2*)(C + (size_t)(jr + 8) * TTBB + nc) = v1;
        }
    }
}

// ---------------------------------------------------------------------------
// Recurrent kernel, 512 threads / 16 warps: warp w owns k-slice
// [w*32, w*32+32). A (W_hh) fragments in registers; warp-local cp.async h
// staging (stage buffer ALIASES the dead W smem); MUFU-free activations;
// fused reduce+cell over 16 partials; flat grid barrier.
// 128 CTAs = 64 ug x 2 bg.
// ---------------------------------------------------------------------------
template <int LAYER>
__global__ __launch_bounds__(RTH)
void lstm_rec_kernel(const float* __restrict__ W_hh,
                     const float* __restrict__ b_ih,
                     const float* __restrict__ b_hh,
                     const float* __restrict__ xg,
                     float* __restrict__ d_out) {
    extern __shared__ char smem_raw[];
    // region [0, 65536): W tiles during init, then h stage (hi at 0, lo at 32K)
    float* part   = (float*)(smem_raw + 65536);             // [16][32][32] = 64KB
    float* c_s    = part + 16 * 32 * 32;                    // [256]
    float* bias_s = c_s + 256;                              // [32]

    const int tid  = threadIdx.x;
    const int ug   = blockIdx.x >> 1;
    const int bg   = blockIdx.x & 1;
    const int lane = tid & 31;
    const int w    = tid >> 5;          // 0..15, k-slice

    const uint32_t sbase = (uint32_t)__cvta_generic_to_shared(smem_raw);

    // --- stage + split W_hh into smem tiles (proven layout; aliased region) ---
    {
        __nv_bfloat16* W_hi = (__nv_bfloat16*)smem_raw;
        __nv_bfloat16* W_lo = W_hi + HH * 32;
        for (int i = tid; i < HH * 32; i += RTH) {
            int kcol = i & 15;
            int r    = (i >> 4) & 15;
            int mt   = (i >> 8) & 1;
            int kk   = i >> 9;
            int rr   = mt * 16 + r;
            int gate = rr >> 3, ul = rr & 7;
            int kg   = kk * 16 + kcol;
            int j    = gate * HH + ug * 8 + ul;
            float v = W_hh[(size_t)j * HH + kg];
            __nv_bfloat16 hi, lo;
            split_bf16(v, hi, lo);
            int off = (kk * 2 + mt) * 512
                    + r * 32
                    + ((((unsigned)kcol >> 3) ^ (((unsigned)r >> 2) & 1u)) << 4)
                    + (kcol & 7) * 2;
            *(__nv_bfloat16*)((char*)W_hi + off) = hi;
            *(__nv_bfloat16*)((char*)W_lo + off) = lo;
        }
    }
    if (tid < 32) {
        int gate = tid >> 3, ul = tid & 7;
        int j = gate * HH + ug * 8 + ul;
        bias_s[tid] = b_ih[j] + b_hh[j];
    }
    if (tid < 256) {
        c_s[tid] = 0.0f;
        int col = ug * 8 + (tid >> 5);
        int bgl = bg * 32 + (tid & 31);
        g_hhi[col * BB + bgl] = __float2bfloat16_rn(0.0f);
        g_hlo[col * BB + bgl] = __float2bfloat16_rn(0.0f);
    }
    __syncthreads();

    // --- A fragments into registers (W smem dead afterwards) ---
    const uint32_t a_off = (uint32_t)((lane & 15) * 32
        + ((((unsigned)lane >> 4) ^ ((((unsigned)lane & 15) >> 2) & 1u)) << 4));
    uint32_t Ahi[2][2][4], Alo[2][2][4];        // [mt][kt][frag]
    #pragma unroll
    for (int kt = 0; kt < 2; ++kt) {
        const int kk = w * 2 + kt;
        #pragma unroll
        for (int mt = 0; mt < 2; ++mt) {
            const uint32_t ta = (uint32_t)((kk * 2 + mt) * 512) + a_off;
            ldsm_x4(Ahi[mt][kt], sbase + ta);
            ldsm_x4(Alo[mt][kt], sbase + 32768 + ta);
        }
    }

    unsigned bar_target = 0;
    if (tid == 0) bar_target = *(volatile unsigned*)&g_bar_epoch[bg];
    grid_barrier(tid, bg, bar_target);   // also orders A-frag loads vs stage reuse

    // stage addresses (aliased region): hi at sbase, lo at sbase + 32768
    // cell identity for fused epilogue (threads 0..255)
    const int ul  = (tid < 256) ? (tid >> 5) : 0;
    const int bcl = lane;
    const int bgl = bg * 32 + bcl;
    const size_t xg_cell = (size_t)(ug * 8 + ul) * TTBB + bgl;

    for (int t = 0; t < TT; ++t) {
        // xg prefetch for this thread's cell
        float xgv[4];
        if (tid < 256) {
            #pragma unroll
            for (int gate = 0; gate < 4; ++gate)
                xgv[gate] = __ldg(xg + (size_t)gate * (HH * TTBB) + xg_cell + (size_t)t * BB);
        }

        // --- WARP-LOCAL h staging: warp w stages its rows [w*32, w*32+32) ---
        const int hoff = (t & 1) * (HH * BB);
        #pragma unroll
        for (int i = 0; i < 4; ++i) {
            int s = lane + i * 32;              // 0..127 within warp region
            int kl = s >> 2, g = s & 3;
            int k = w * 32 + kl;
            const int so = hoff + k * BB + bg * 32 + g * 8;
            uint32_t doff = (uint32_t)(k * 64 + ((((unsigned)g) ^ (((unsigned)k >> 1) & 3u)) << 4));
            cp_async16(sbase + doff, g_hhi + so);
            cp_async16(sbase + 32768 + doff, g_hlo + so);
        }
        cp_commit();
        cp_wait<0>();
        __syncwarp();

        // --- MMA: A from regs, B via ldsm from own staged region ---
        float acc[2][4][4];
        #pragma unroll
        for (int mt = 0; mt < 2; ++mt)
            #pragma unroll
            for (int j = 0; j < 4; ++j)
                #pragma unroll
                for (int q = 0; q < 4; ++q) acc[mt][j][q] = 0.0f;

        #pragma unroll
        for (int kt = 0; kt < 2; ++kt) {
            const uint32_t kabs = (uint32_t)(w * 32 + kt * 16 + (lane & 15));
            const uint32_t bswz = (kabs >> 1) & 3u;
            const uint32_t brow = kabs * 64;
            uint32_t bhi[4][2], blo[4][2];
            #pragma unroll
            for (int j = 0; j < 4; ++j) {
                const uint32_t go = (((uint32_t)j) ^ bswz) << 4;
                ldsm_x2t(bhi[j], sbase + brow + go);
                ldsm_x2t(blo[j], sbase + 32768 + brow + go);
            }
            #pragma unroll
            for (int mt = 0; mt < 2; ++mt)
                #pragma unroll
                for (int j = 0; j < 4; ++j) {
                    mma_bf16(acc[mt][j], Ahi[mt][kt], bhi[j]);
                    mma_bf16(acc[mt][j], Ahi[mt][kt], blo[j]);
                    mma_bf16(acc[mt][j], Alo[mt][kt], bhi[j]);
                }
        }

        // --- scatter warp partials: part[w][32r][32b] ---
        {
            const int row0 = lane >> 2;
            const int col0 = (lane & 3) * 2;
            float* pw = part + w * 1024;
            #pragma unroll
            for (int mt = 0; mt < 2; ++mt)
                #pragma unroll
                for (int j = 0; j < 4; ++j) {
                    float* p = pw + (mt * 16 + row0) * 32 + j * 8 + col0;
                    p[0]          = acc[mt][j][0];
                    p[1]          = acc[mt][j][1];
                    p[8 * 32]     = acc[mt][j][2];
                    p[8 * 32 + 1] = acc[mt][j][3];
                }
        }
        __syncthreads();

        // --- fused reduce (16 partials) + cell update (threads 0..255) ---
        if (tid < 256) {
            float gsum[4];
            #pragma unroll
            for (int gate = 0; gate < 4; ++gate) {
                const int rr = gate * 8 + ul;
                float s = xgv[gate] + bias_s[rr];
                #pragma unroll
                for (int p = 0; p < 16; ++p)
                    s += part[p * 1024 + rr * 32 + bcl];
                gsum[gate] = s;
            }
            const float i_ = fast_sigmoid(gsum[0]);
            const float f_ = fast_sigmoid(gsum[1]);
            const float g_ = fast_tanh(gsum[2]);
            const float o_ = fast_sigmoid(gsum[3]);
            const float cn = f_ * c_s[tid] + i_ * g_;
            c_s[tid] = cn;
            const float h = o_ * fast_tanh(cn);
            const int col = ug * 8 + ul;
            __nv_bfloat16 hi, lo;
            split_bf16(h, hi, lo);
            const int hdst = ((t + 1) & 1) * (HH * BB) + col * BB + bgl;
            g_hhi[hdst] = hi;
            g_hlo[hdst] = lo;
            if (LAYER == 0) {
                const size_t oo = (size_t)col * TTBB + t * BB + bgl;
                g_o0hi[oo] = hi;
                g_o0lo[oo] = lo;
            }
            if (t == TT - 1) {
                d_out[64 + LAYER * (BB * HH) + (size_t)bgl * HH + col] = h;
                d_out[64 + 2 * (BB * HH) + LAYER * (BB * HH) + (size_t)bgl * HH + col] = cn;
            }
        }
        grid_barrier(tid, bg, bar_target);
    }
}

// ---------------------------------------------------------------------------
// FC: out[b] = dot(hn1[b,:], fc_w) + fc_b
// ---------------------------------------------------------------------------
__global__ void fc_kernel(const float* __restrict__ fc_w,
                          const float* __restrict__ fc_b,
                          float* __restrict__ d_out) {
    const int b = blockIdx.x;
    const int tid = threadIdx.x;
    const float* h = d_out + 64 + (BB * HH) + (size_t)b * HH;
    float s = 0.0f;
    for (int k = tid; k < HH; k += 128) s += h[k] * fc_w[k];
    #pragma unroll
    for (int off = 16; off > 0; off >>= 1) s += __shfl_down_sync(0xffffffffu, s, off);
    __shared__ float wsum[4];
    if ((tid & 31) == 0) wsum[tid >> 5] = s;
    __syncthreads();
    if (tid == 0) d_out[b] = wsum[0] + wsum[1] + wsum[2] + wsum[3] + fc_b[0];
}

// ---------------------------------------------------------------------------
// Launch — ordered so lstm_rec_kernel<0> is the 4th kernel (ncu capture slot)
// ---------------------------------------------------------------------------
extern "C" void kernel_launch(void* const* d_in, const int* in_sizes, int n_in,
                              void* d_out, int out_size) {
    const float* x     = (const float*)d_in[0];
    const float* W_ih0 = (const float*)d_in[1];
    const float* W_hh0 = (const float*)d_in[2];
    const float* b_ih0 = (const float*)d_in[3];
    const float* b_hh0 = (const float*)d_in[4];
    const float* W_ih1 = (const float*)d_in[5];
    const float* W_hh1 = (const float*)d_in[6];
    const float* b_ih1 = (const float*)d_in[7];
    const float* b_hh1 = (const float*)d_in[8];
    const float* fc_w  = (const float*)d_in[9];
    const float* fc_b  = (const float*)d_in[10];
    float* out = (float*)d_out;

    __nv_bfloat16 *wih0hi, *wih0lo, *wih1hi, *wih1lo, *xhi, *xlo, *o0hi, *o0lo;
    float *xg0, *xg1;
    cudaGetSymbolAddress((void**)&wih0hi, g_wih0hi);
    cudaGetSymbolAddress((void**)&wih0lo, g_wih0lo);
    cudaGetSymbolAddress((void**)&wih1hi, g_wih1hi);
    cudaGetSymbolAddress((void**)&wih1lo, g_wih1lo);
    cudaGetSymbolAddress((void**)&xhi, g_xhi);
    cudaGetSymbolAddress((void**)&xlo, g_xlo);
    cudaGetSymbolAddress((void**)&o0hi, g_o0hi);
    cudaGetSymbolAddress((void**)&o0lo, g_o0lo);
    cudaGetSymbolAddress((void**)&xg0, g_xg0);
    cudaGetSymbolAddress((void**)&xg1, g_xg1);

    const int smem_tr   = 256 * 65 * 4;
    const int smem_gemm = 65536;
    const int smem_rec  = 65536                  // W tiles / h stage (aliased)
                        + 16 * 32 * 32 * 4       // part
                        + 256 * 4 + 32 * 4 + 128;

    cudaFuncSetAttribute(transpose_x_kernel,
                         cudaFuncAttributeMaxDynamicSharedMemorySize, smem_tr);
    cudaFuncSetAttribute(gemm_xg_kernel<DD>,
                         cudaFuncAttributeMaxDynamicSharedMemorySize, smem_gemm);
    cudaFuncSetAttribute(gemm_xg_kernel<HH>,
                         cudaFuncAttributeMaxDynamicSharedMemorySize, smem_gemm);
    cudaFuncSetAttribute(lstm_rec_kernel<0>,
                         cudaFuncAttributeMaxDynamicSharedMemorySize, smem_rec);
    cudaFuncSetAttribute(lstm_rec_kernel<1>,
                         cudaFuncAttributeMaxDynamicSharedMemorySize, smem_rec);

    // Launch order puts rec<0> in slot 4 for the ncu capture.
    split_w_kernel<<<256, 256>>>(W_ih0, wih0hi, wih0lo, 4 * HH * DD);       // 1
    transpose_x_kernel<<<TT, NTH, smem_tr>>>(x);                            // 2
    dim3 ggrid(TTBB / 128, 16);
    gemm_xg_kernel<DD><<<ggrid, NTH, smem_gemm>>>(wih0hi, wih0lo, xhi, xlo, xg0);  // 3
    lstm_rec_kernel<0><<<NCTA, RTH, smem_rec>>>(W_hh0, b_ih0, b_hh0, xg0, out);    // 4
    split_w_kernel<<<256, 256>>>(W_ih1, wih1hi, wih1lo, 4 * HH * HH);       // 5
    gemm_xg_kernel<HH><<<ggrid, NTH, smem_gemm>>>(wih1hi, wih1lo, o0hi, o0lo, xg1);// 6
    lstm_rec_kernel<1><<<NCTA, RTH, smem_rec>>>(W_hh1, b_ih1, b_hh1, xg1, out);    // 7
    fc_kernel<<<BB, 128>>>(fc_w, fc_b, out);                                // 8
}

// round 17
// speedup vs baseline: 1.3682x; 1.3682x over previous
#include <cuda_runtime.h>
#include <cuda_bf16.h>
#include <cstdint>
#include <math.h>

#define BB    64
#define TT    512
#define DD    256
#define HH    512
#define TTBB  (TT * BB)     // 32768
#define NCTA  128
#define NGRP  64
#define NTH   256

// ---------------------------------------------------------------------------
// Global scratch
// ---------------------------------------------------------------------------
__device__ __nv_bfloat16 g_xhi[DD * TTBB];      // x planes [d][t][b]
__device__ __nv_bfloat16 g_xlo[DD * TTBB];
__device__ __nv_bfloat16 g_o0hi[HH * TTBB];     // layer0 out planes [h][t][b]
__device__ __nv_bfloat16 g_o0lo[HH * TTBB];
__device__ __nv_bfloat16 g_h0hi[2 * HH * BB];   // h0 planes [buf][h][b]
__device__ __nv_bfloat16 g_h0lo[2 * HH * BB];
__device__ __nv_bfloat16 g_h1hi[2 * HH * BB];   // h1 planes [buf][h][b]
__device__ __nv_bfloat16 g_h1lo[2 * HH * BB];
__device__ __nv_bfloat16 g_wih0hi[4 * HH * DD];
__device__ __nv_bfloat16 g_wih0lo[4 * HH * DD];
__device__ float g_xg0[(size_t)4 * HH * TTBB];
__device__ unsigned g_bar_count[2];
__device__ unsigned g_bar_epoch[2];

// ---------------------------------------------------------------------------
// Helpers
// ---------------------------------------------------------------------------
__device__ __forceinline__ void ldsm_x4(uint32_t (&r)[4], uint32_t addr) {
    asm volatile("ldmatrix.sync.aligned.m8n8.x4.shared.b16 {%0,%1,%2,%3}, [%4];\n"
                 : "=r"(r[0]), "=r"(r[1]), "=r"(r[2]), "=r"(r[3]) : "r"(addr));
}
__device__ __forceinline__ void ldsm_x2t(uint32_t (&r)[2], uint32_t addr) {
    asm volatile("ldmatrix.sync.aligned.m8n8.x2.trans.shared.b16 {%0,%1}, [%2];\n"
                 : "=r"(r[0]), "=r"(r[1]) : "r"(addr));
}
__device__ __forceinline__ void mma_bf16(float (&d)[4], const uint32_t (&a)[4],
                                         const uint32_t (&b)[2]) {
    asm volatile("mma.sync.aligned.m16n8k16.row.col.f32.bf16.bf16.f32 "
                 "{%0,%1,%2,%3}, {%4,%5,%6,%7}, {%8,%9}, {%0,%1,%2,%3};\n"
                 : "+f"(d[0]), "+f"(d[1]), "+f"(d[2]), "+f"(d[3])
                 : "r"(a[0]), "r"(a[1]), "r"(a[2]), "r"(a[3]),
                   "r"(b[0]), "r"(b[1]));
}
__device__ __forceinline__ void split_bf16(float v, __nv_bfloat16& hi, __nv_bfloat16& lo) {
    hi = __float2bfloat16_rn(v);
    lo = __float2bfloat16_rn(v - __bfloat162float(hi));
}
__device__ __forceinline__ void cp_async16(uint32_t dst, const void* src) {
    asm volatile("cp.async.cg.shared.global [%0], [%1], 16;\n" :: "r"(dst), "l"(src));
}
__device__ __forceinline__ void cp_commit() {
    asm volatile("cp.async.commit_group;\n");
}
template <int N>
__device__ __forceinline__ void cp_wait() {
    asm volatile("cp.async.wait_group %0;\n" :: "n"(N));
}

// ---------------------------------------------------------------------------
// MUFU-free activation math
// ---------------------------------------------------------------------------
__device__ __forceinline__ float fast_exp(float x) {
    float z = x * 1.4426950408889634f;
    float nf = rintf(z);
    float f = z - nf;
    float p = 1.535336188319500e-4f;
    p = fmaf(p, f, 1.339887440266574e-3f);
    p = fmaf(p, f, 9.618437357674640e-3f);
    p = fmaf(p, f, 5.550332471162809e-2f);
    p = fmaf(p, f, 2.402264791363012e-1f);
    p = fmaf(p, f, 6.931472028550421e-1f);
    p = fmaf(p, f, 1.0f);
    int n = (int)nf;
    return p * __int_as_float((n + 127) << 23);
}
__device__ __forceinline__ float fast_rcp(float x) {
    float y = __int_as_float(0x7EF311C3 - __float_as_int(x));
    y = y * (2.0f - x * y);
    y = y * (2.0f - x * y);
    y = y * (2.0f - x * y);
    return y;
}
__device__ __forceinline__ float fast_sigmoid(float x) {
    x = fminf(30.0f, fmaxf(-30.0f, x));
    return fast_rcp(1.0f + fast_exp(-x));
}
__device__ __forceinline__ float fast_tanh(float x) {
    x = fminf(15.0f, fmaxf(-15.0f, x));
    float e = fast_exp(2.0f * x);
    return (e - 1.0f) * fast_rcp(e + 1.0f);
}

// ---------------------------------------------------------------------------
// Flat grid barrier (64 CTAs per group, all co-resident; proven)
// ---------------------------------------------------------------------------
__device__ __forceinline__ void grid_barrier(int tid, int grp, unsigned& target) {
    __threadfence();
    __syncthreads();
    target += 1;
    if (tid == 0) {
        unsigned old = atomicAdd(&g_bar_count[grp], 1u);
        if (old == NGRP - 1) {
            atomicExch(&g_bar_count[grp], 0u);
            __threadfence();
            atomicAdd(&g_bar_epoch[grp], 1u);
        } else {
            while ((int)(*(volatile unsigned*)&g_bar_epoch[grp] - target) < 0) {
                __nanosleep(32);
            }
            __threadfence();
        }
    }
    __syncthreads();
}

// ---------------------------------------------------------------------------
// Split fp32 weights into bf16 hi/lo planes
// ---------------------------------------------------------------------------
__global__ void split_w_kernel(const float* __restrict__ W,
                               __nv_bfloat16* __restrict__ hi,
                               __nv_bfloat16* __restrict__ lo, int n) {
    for (int i = blockIdx.x * blockDim.x + threadIdx.x; i < n; i += gridDim.x * blockDim.x) {
        __nv_bfloat16 h, l;
        split_bf16(W[i], h, l);
        hi[i] = h;
        lo[i] = l;
    }
}

// ---------------------------------------------------------------------------
// Transpose + split x: [b][t][d] -> planes [d][t][b]
// ---------------------------------------------------------------------------
__global__ void transpose_x_kernel(const float* __restrict__ x) {
    extern __shared__ float sm[];
    const int t = blockIdx.x;
    const int tid = threadIdx.x;
    for (int i = tid; i < BB * DD; i += NTH) {
        int b = i >> 8;
        int d = i & 255;
        sm[d * 65 + b] = x[(size_t)b * (TT * DD) + (size_t)t * DD + d];
    }
    __syncthreads();
    for (int i = tid; i < DD * BB; i += NTH) {
        int d = i >> 6;
        int b = i & 63;
        float v = sm[d * 65 + b];
        __nv_bfloat16 hi, lo;
        split_bf16(v, hi, lo);
        const size_t idx = (size_t)d * TTBB + t * BB + b;
        g_xhi[idx] = hi;
        g_xlo[idx] = lo;
    }
}

// ---------------------------------------------------------------------------
// Bulk GEMM for xg0 (unchanged, proven: tensor 62%)
// ---------------------------------------------------------------------------
template <int K>
__global__ __launch_bounds__(NTH)
void gemm_xg_kernel(const __nv_bfloat16* __restrict__ Whi,
                    const __nv_bfloat16* __restrict__ Wlo,
                    const __nv_bfloat16* __restrict__ Xhi,
                    const __nv_bfloat16* __restrict__ Xlo,
                    float* __restrict__ C) {
    constexpr int NKC = K / 32;
    extern __shared__ char sm_raw[];
    const uint32_t sbase = (uint32_t)__cvta_generic_to_shared(sm_raw);

    const int tid  = threadIdx.x;
    const int lane = tid & 31;
    const int w    = tid >> 5;
    const int wj   = w >> 2;
    const int wn0g = (w & 3) * 4;
    const int j0   = blockIdx.y * 128;
    const int n0   = blockIdx.x * 128;

    auto stage = [&](int kc, int buf) {
        const uint32_t bb = sbase + buf * 32768;
        #pragma unroll
        for (int q = 0; q < 4; ++q) {
            int idx = tid + q * 256;
            int p   = idx >> 9;
            int rem = idx & 511;
            int jl  = rem >> 2;
            int kh  = (rem >> 1) & 1;
            int g   = rem & 1;
            const __nv_bfloat16* src = (p ? Wlo : Whi)
                + (size_t)(j0 + jl) * K + kc * 32 + kh * 16 + g * 8;
            uint32_t dst = bb + p * 8192
                + (((jl >> 4) * 2 + kh) * 512)
                + (jl & 15) * 32
                + ((((unsigned)g) ^ (((unsigned)jl >> 2) & 1u)) << 4);
            cp_async16(dst, src);
        }
        #pragma unroll
        for (int q = 0; q < 4; ++q) {
            int idx = tid + q * 256;
            int p   = idx >> 9;
            int rem = idx & 511;
            int k   = rem >> 4;
            int g   = rem & 15;
            const __nv_bfloat16* src = (p ? Xlo : Xhi)
                + (size_t)(kc * 32 + k) * TTBB + n0 + g * 8;
            uint32_t dst = bb + 16384 + p * 8192 + k * 256
                + ((((unsigned)g) ^ ((unsigned)k & 7u)) << 4);
            cp_async16(dst, src);
        }
        cp_commit();
    };

    const uint32_t a_off = (uint32_t)((lane & 15) * 32
        + ((((unsigned)lane >> 4) ^ ((((unsigned)lane & 15) >> 2) & 1u)) << 4));

    float acc[4][4][4];
    #pragma unroll
    for (int mj = 0; mj < 4; ++mj)
        #pragma unroll
        for (int nj = 0; nj < 4; ++nj)
            #pragma unroll
            for (int q = 0; q < 4; ++q) acc[mj][nj][q] = 0.0f;

    stage(0, 0);
    for (int kc = 0; kc < NKC; ++kc) {
        if (kc + 1 < NKC) {
            stage(kc + 1, (kc + 1) & 1);
            cp_wait<1>();
        } else {
            cp_wait<0>();
        }
        __syncthreads();

        const uint32_t bb = sbase + (kc & 1) * 32768;
        const uint32_t Ahi_b = bb, Alo_b = bb + 8192;
        const uint32_t Bhi_b = bb + 16384, Blo_b = bb + 24576;

        #pragma unroll
        for (int kt = 0; kt < 2; ++kt) {
            uint32_t ahi[4][4], alo[4][4], bhi[4][2], blo[4][2];
            #pragma unroll
            for (int mj = 0; mj < 4; ++mj) {
                const uint32_t ta = (uint32_t)(((wj * 4 + mj) * 2 + kt) * 512) + a_off;
                ldsm_x4(ahi[mj], Ahi_b + ta);
                ldsm_x4(alo[mj], Alo_b + ta);
            }
            const uint32_t krow = (uint32_t)(kt * 16 + (lane & 15));
            #pragma unroll
            for (int nj = 0; nj < 4; ++nj) {
                const uint32_t go = (((uint32_t)(wn0g + nj)) ^ (krow & 7u)) << 4;
                ldsm_x2t(bhi[nj], Bhi_b + krow * 256 + go);
                ldsm_x2t(blo[nj], Blo_b + krow * 256 + go);
            }
            #pragma unroll
            for (int mj = 0; mj < 4; ++mj)
                #pragma unroll
                for (int nj = 0; nj < 4; ++nj) {
                    mma_bf16(acc[mj][nj], ahi[mj], bhi[nj]);
                    mma_bf16(acc[mj][nj], ahi[mj], blo[nj]);
                    mma_bf16(acc[mj][nj], alo[mj], bhi[nj]);
                }
        }
        __syncthreads();
    }

    #pragma unroll
    for (int mj = 0; mj < 4; ++mj) {
        const int jr = j0 + wj * 64 + mj * 16 + (lane >> 2);
        #pragma unroll
        for (int nj = 0; nj < 4; ++nj) {
            const int nc = n0 + (w & 3) * 32 + nj * 8 + (lane & 3) * 2;
            float2 v0 = make_float2(acc[mj][nj][0], acc[mj][nj][1]);
            float2 v1 = make_float2(acc[mj][nj][2], acc[mj][nj][3]);
            *(float2*)(C + (size_t)jr * TTBB + nc)       = v0;
            *(float2*)(C + (size_t)(jr + 8) * TTBB + nc) = v1;
        }
    }
}

// ---------------------------------------------------------------------------
// FUSED two-layer recurrent kernel. Iteration i: L0 step i and L1 step i-1
// run back-to-back with ONE barrier per iteration (513 total vs 1024).
// 128 CTAs = 64 ug x 2 bg; 8 warps; warp w owns k [w*64, w*64+64).
// A0 (W_hh0) fragments in registers; W_ih1/W_hh1 tiles resident in smem;
// one 64KB stage region reused per-warp sequentially (h0 -> h1 -> out0).
// smem: stage 64K | Wih1 64K | Whh1 64K | part 32K | c0,c1,bias = 231,680B.
// ---------------------------------------------------------------------------
__global__ __launch_bounds__(NTH)
void lstm_fused_kernel(const float* __restrict__ W_hh0,
                       const float* __restrict__ b_ih0,
                       const float* __restrict__ b_hh0,
                       const float* __restrict__ W_ih1,
                       const float* __restrict__ W_hh1,
                       const float* __restrict__ b_ih1,
                       const float* __restrict__ b_hh1,
                       const float* __restrict__ xg,
                       float* __restrict__ d_out) {
    extern __shared__ char smem_raw[];
    const uint32_t sbase = (uint32_t)__cvta_generic_to_shared(smem_raw);
    // stage region: hi at sbase, lo at sbase+32768 (init: W_hh0 tiles)
    const uint32_t sWih1 = sbase + 65536;     // hi, lo at +32768
    const uint32_t sWhh1 = sbase + 131072;
    float* part   = (float*)(smem_raw + 196608);   // [8][32][32] = 32KB
    float* c0_s   = part + 8 * 32 * 32;            // [256]
    float* c1_s   = c0_s + 256;                    // [256]
    float* bias0_s = c1_s + 256;                   // [32]
    float* bias1_s = bias0_s + 32;                 // [32]

    const int tid  = threadIdx.x;
    const int ug   = blockIdx.x >> 1;
    const int bg   = blockIdx.x & 1;
    const int lane = tid & 31;
    const int w    = tid >> 5;

    // --- init: stage W tiles (proven layout) ---
    auto stage_w_tiles = [&](const float* W, char* dhi_base) {
        __nv_bfloat16* Whi = (__nv_bfloat16*)dhi_base;
        __nv_bfloat16* Wlo = Whi + HH * 32;
        for (int i = tid; i < HH * 32; i += NTH) {
            int kcol = i & 15;
            int r    = (i >> 4) & 15;
            int mt   = (i >> 8) & 1;
            int kk   = i >> 9;
            int rr   = mt * 16 + r;
            int gate = rr >> 3, ul = rr & 7;
            int kg   = kk * 16 + kcol;
            int j    = gate * HH + ug * 8 + ul;
            float v = W[(size_t)j * HH + kg];
            __nv_bfloat16 hi, lo;
            split_bf16(v, hi, lo);
            int off = (kk * 2 + mt) * 512
                    + r * 32
                    + ((((unsigned)kcol >> 3) ^ (((unsigned)r >> 2) & 1u)) << 4)
                    + (kcol & 7) * 2;
            *(__nv_bfloat16*)((char*)Whi + off) = hi;
            *(__nv_bfloat16*)((char*)Wlo + off) = lo;
        }
    };
    stage_w_tiles(W_hh0, smem_raw);            // into stage region (temporary)
    stage_w_tiles(W_ih1, smem_raw + 65536);
    stage_w_tiles(W_hh1, smem_raw + 131072);
    if (tid < 32) {
        int gate = tid >> 3, ul = tid & 7;
        int j = gate * HH + ug * 8 + ul;
        bias0_s[tid] = b_ih0[j] + b_hh0[j];
        bias1_s[tid] = b_ih1[j] + b_hh1[j];
    }
    c0_s[tid] = 0.0f;
    c1_s[tid] = 0.0f;
    {   // zero h0/h1 buf 0 for our slice
        int col = ug * 8 + (tid >> 5);
        int bgl = bg * 32 + (tid & 31);
        __nv_bfloat16 z = __float2bfloat16_rn(0.0f);
        g_h0hi[col * BB + bgl] = z;
        g_h0lo[col * BB + bgl] = z;
        g_h1hi[col * BB + bgl] = z;
        g_h1lo[col * BB + bgl] = z;
    }
    __syncthreads();

    // --- A0 fragments into registers (stage region dead afterwards) ---
    const uint32_t a_off = (uint32_t)((lane & 15) * 32
        + ((((unsigned)lane >> 4) ^ ((((unsigned)lane & 15) >> 2) & 1u)) << 4));
    uint32_t A0hi[2][4][4], A0lo[2][4][4];
    #pragma unroll
    for (int kt = 0; kt < 4; ++kt) {
        const int kk = w * 4 + kt;
        #pragma unroll
        for (int mt = 0; mt < 2; ++mt) {
            const uint32_t ta = (uint32_t)((kk * 2 + mt) * 512) + a_off;
            ldsm_x4(A0hi[mt][kt], sbase + ta);
            ldsm_x4(A0lo[mt][kt], sbase + 32768 + ta);
        }
    }

    unsigned bar_target = 0;
    if (tid == 0) bar_target = *(volatile unsigned*)&g_bar_epoch[bg];
    grid_barrier(tid, bg, bar_target);

    // warp-local staging of one K=512 input into the stage region.
    // rows [w*64, w*64+64), swizzled (proven R15 layout).
    auto stage_hx = [&](const __nv_bfloat16* srch, const __nv_bfloat16* srcl,
                        int row_stride, int col_off) {
        #pragma unroll
        for (int i = 0; i < 8; ++i) {
            int s = lane + i * 32;
            int kl = s >> 2, g = s & 3;
            int k = w * 64 + kl;
            const size_t so = (size_t)k * row_stride + col_off + g * 8;
            uint32_t doff = (uint32_t)(k * 64 + ((((unsigned)g) ^ (((unsigned)k >> 1) & 3u)) << 4));
            cp_async16(sbase + doff, srch + so);
            cp_async16(sbase + 32768 + doff, srcl + so);
        }
        cp_commit();
    };

    // B fragments + MMA over the staged region. A either from regs or smem.
    auto mma_regA = [&](float (&acc)[2][4][4]) {
        #pragma unroll
        for (int kt = 0; kt < 4; ++kt) {
            const uint32_t kabs = (uint32_t)((w * 4 + kt) * 16 + (lane & 15));
            const uint32_t bswz = (kabs >> 1) & 3u;
            const uint32_t brow = kabs * 64;
            uint32_t bhi[4][2], blo[4][2];
            #pragma unroll
            for (int j = 0; j < 4; ++j) {
                const uint32_t go = (((uint32_t)j) ^ bswz) << 4;
                ldsm_x2t(bhi[j], sbase + brow + go);
                ldsm_x2t(blo[j], sbase + 32768 + brow + go);
            }
            #pragma unroll
            for (int mt = 0; mt < 2; ++mt)
                #pragma unroll
                for (int j = 0; j < 4; ++j) {
                    mma_bf16(acc[mt][j], A0hi[mt][kt], bhi[j]);
                    mma_bf16(acc[mt][j], A0hi[mt][kt], blo[j]);
                    mma_bf16(acc[mt][j], A0lo[mt][kt], bhi[j]);
                }
        }
    };
    auto mma_smemA = [&](uint32_t aW, float (&acc)[2][4][4]) {
        #pragma unroll
        for (int kt = 0; kt < 4; ++kt) {
            const uint32_t kabs = (uint32_t)((w * 4 + kt) * 16 + (lane & 15));
            const uint32_t bswz = (kabs >> 1) & 3u;
            const uint32_t brow = kabs * 64;
            uint32_t bhi[4][2], blo[4][2];
            #pragma unroll
            for (int j = 0; j < 4; ++j) {
                const uint32_t go = (((uint32_t)j) ^ bswz) << 4;
                ldsm_x2t(bhi[j], sbase + brow + go);
                ldsm_x2t(blo[j], sbase + 32768 + brow + go);
            }
            #pragma unroll
            for (int mt = 0; mt < 2; ++mt) {
                uint32_t ahi[4], alo[4];
                const uint32_t ta = (uint32_t)(((w * 4 + kt) * 2 + mt) * 512) + a_off;
                ldsm_x4(ahi, aW + ta);
                ldsm_x4(alo, aW + 32768 + ta);
                #pragma unroll
                for (int j = 0; j < 4; ++j) {
                    mma_bf16(acc[mt][j], ahi, bhi[j]);
                    mma_bf16(acc[mt][j], ahi, blo[j]);
                    mma_bf16(acc[mt][j], alo, bhi[j]);
                }
            }
        }
    };
    auto scatter_part = [&](float (&acc)[2][4][4]) {
        const int row0 = lane >> 2;
        const int col0 = (lane & 3) * 2;
        float* pw = part + w * 1024;
        #pragma unroll
        for (int mt = 0; mt < 2; ++mt)
            #pragma unroll
            for (int j = 0; j < 4; ++j) {
                float* p = pw + (mt * 16 + row0) * 32 + j * 8 + col0;
                p[0]          = acc[mt][j][0];
                p[1]          = acc[mt][j][1];
                p[8 * 32]     = acc[mt][j][2];
                p[8 * 32 + 1] = acc[mt][j][3];
            }
    };

    // cell identity (threads 0..255 = all): warp = unit, lane = batch
    const int ul  = tid >> 5;
    const int bcl = lane;
    const int bgl = bg * 32 + bcl;
    const int col = ug * 8 + ul;
    const size_t xg_cell = (size_t)col * TTBB + bgl;

    for (int i = 0; i <= TT; ++i) {
        const bool doL0 = (i < TT);
        const bool doL1 = (i >= 1);

        if (doL0) {
            // ---------- Layer 0, step t0 = i ----------
            float xgv[4];
            #pragma unroll
            for (int gate = 0; gate < 4; ++gate)
                xgv[gate] = __ldg(xg + (size_t)gate * (HH * TTBB) + xg_cell + (size_t)i * BB);

            stage_hx(g_h0hi + (i & 1) * (HH * BB), g_h0lo + (i & 1) * (HH * BB),
                     BB, bg * 32);
            cp_wait<0>();
            __syncwarp();

            float acc[2][4][4];
            #pragma unroll
            for (int mt = 0; mt < 2; ++mt)
                #pragma unroll
                for (int j = 0; j < 4; ++j)
                    #pragma unroll
                    for (int q = 0; q < 4; ++q) acc[mt][j][q] = 0.0f;
            mma_regA(acc);

            // issue h1 staging now (covered by L0 epilogue)
            if (doL1)
                stage_hx(g_h1hi + ((i - 1) & 1) * (HH * BB),
                         g_h1lo + ((i - 1) & 1) * (HH * BB), BB, bg * 32);

            scatter_part(acc);
            __syncthreads();

            {   // fused reduce + cell0
                float gsum[4];
                #pragma unroll
                for (int gate = 0; gate < 4; ++gate) {
                    const int rr = gate * 8 + ul;
                    float s = xgv[gate] + bias0_s[rr];
                    #pragma unroll
                    for (int p = 0; p < 8; ++p)
                        s += part[p * 1024 + rr * 32 + bcl];
                    gsum[gate] = s;
                }
                const float i_ = fast_sigmoid(gsum[0]);
                const float f_ = fast_sigmoid(gsum[1]);
                const float g_ = fast_tanh(gsum[2]);
                const float o_ = fast_sigmoid(gsum[3]);
                const float cn = f_ * c0_s[tid] + i_ * g_;
                c0_s[tid] = cn;
                const float h = o_ * fast_tanh(cn);
                __nv_bfloat16 hi, lo;
                split_bf16(h, hi, lo);
                const int hdst = ((i + 1) & 1) * (HH * BB) + col * BB + bgl;
                g_h0hi[hdst] = hi;
                g_h0lo[hdst] = lo;
                const size_t oo = (size_t)col * TTBB + (size_t)i * BB + bgl;
                g_o0hi[oo] = hi;
                g_o0lo[oo] = lo;
                if (i == TT - 1) {
                    d_out[64 + (size_t)bgl * HH + col] = h;                    // hn L0
                    d_out[64 + 2 * (BB * HH) + (size_t)bgl * HH + col] = cn;   // cn L0
                }
            }
            __syncthreads();   // part consumed before L1 overwrites
        } else if (doL1) {
            // no L0 phase: issue h1 staging here (latency exposed once)
            stage_hx(g_h1hi + ((i - 1) & 1) * (HH * BB),
                     g_h1lo + ((i - 1) & 1) * (HH * BB), BB, bg * 32);
        }

        if (doL1) {
            // ---------- Layer 1, step t1 = i-1 ----------
            const int t1 = i - 1;
            cp_wait<0>();
            __syncwarp();

            float acc[2][4][4];
            #pragma unroll
            for (int mt = 0; mt < 2; ++mt)
                #pragma unroll
                for (int j = 0; j < 4; ++j)
                    #pragma unroll
                    for (int q = 0; q < 4; ++q) acc[mt][j][q] = 0.0f;
            mma_smemA(sWhh1, acc);                  // h1 contribution

            // stage out0[t1] (row stride TTBB, col offset t1*BB + bg*32)
            stage_hx(g_o0hi, g_o0lo, TTBB, t1 * BB + bg * 32);
            cp_wait<0>();
            __syncwarp();
            mma_smemA(sWih1, acc);                  // W_ih1 @ out0 contribution

            scatter_part(acc);
            __syncthreads();

            {   // fused reduce + cell1
                float gsum[4];
                #pragma unroll
                for (int gate = 0; gate < 4; ++gate) {
                    const int rr = gate * 8 + ul;
                    float s = bias1_s[rr];
                    #pragma unroll
                    for (int p = 0; p < 8; ++p)
                        s += part[p * 1024 + rr * 32 + bcl];
                    gsum[gate] = s;
                }
                const float i_ = fast_sigmoid(gsum[0]);
                const float f_ = fast_sigmoid(gsum[1]);
                const float g_ = fast_tanh(gsum[2]);
                const float o_ = fast_sigmoid(gsum[3]);
                const float cn = f_ * c1_s[tid] + i_ * g_;
                c1_s[tid] = cn;
                const float h = o_ * fast_tanh(cn);
                __nv_bfloat16 hi, lo;
                split_bf16(h, hi, lo);
                const int hdst = (i & 1) * (HH * BB) + col * BB + bgl;
                g_h1hi[hdst] = hi;
                g_h1lo[hdst] = lo;
                if (t1 == TT - 1) {
                    d_out[64 + (BB * HH) + (size_t)bgl * HH + col] = h;                  // hn L1
                    d_out[64 + 3 * (BB * HH) + (size_t)bgl * HH + col] = cn;             // cn L1
                }
            }
        }

        grid_barrier(tid, bg, bar_target);
    }
}

// ---------------------------------------------------------------------------
// FC: out[b] = dot(hn1[b,:], fc_w) + fc_b
// ---------------------------------------------------------------------------
__global__ void fc_kernel(const float* __restrict__ fc_w,
                          const float* __restrict__ fc_b,
                          float* __restrict__ d_out) {
    const int b = blockIdx.x;
    const int tid = threadIdx.x;
    const float* h = d_out + 64 + (BB * HH) + (size_t)b * HH;
    float s = 0.0f;
    for (int k = tid; k < HH; k += 128) s += h[k] * fc_w[k];
    #pragma unroll
    for (int off = 16; off > 0; off >>= 1) s += __shfl_down_sync(0xffffffffu, s, off);
    __shared__ float wsum[4];
    if ((tid & 31) == 0) wsum[tid >> 5] = s;
    __syncthreads();
    if (tid == 0) d_out[b] = wsum[0] + wsum[1] + wsum[2] + wsum[3] + fc_b[0];
}

// ---------------------------------------------------------------------------
// Launch — fused rec kernel sits in slot 4 (ncu capture slot)
// ---------------------------------------------------------------------------
extern "C" void kernel_launch(void* const* d_in, const int* in_sizes, int n_in,
                              void* d_out, int out_size) {
    const float* x     = (const float*)d_in[0];
    const float* W_ih0 = (const float*)d_in[1];
    const float* W_hh0 = (const float*)d_in[2];
    const float* b_ih0 = (const float*)d_in[3];
    const float* b_hh0 = (const float*)d_in[4];
    const float* W_ih1 = (const float*)d_in[5];
    const float* W_hh1 = (const float*)d_in[6];
    const float* b_ih1 = (const float*)d_in[7];
    const float* b_hh1 = (const float*)d_in[8];
    const float* fc_w  = (const float*)d_in[9];
    const float* fc_b  = (const float*)d_in[10];
    float* out = (float*)d_out;

    __nv_bfloat16 *wih0hi, *wih0lo, *xhi, *xlo;
    float *xg0;
    cudaGetSymbolAddress((void**)&wih0hi, g_wih0hi);
    cudaGetSymbolAddress((void**)&wih0lo, g_wih0lo);
    cudaGetSymbolAddress((void**)&xhi, g_xhi);
    cudaGetSymbolAddress((void**)&xlo, g_xlo);
    cudaGetSymbolAddress((void**)&xg0, g_xg0);

    const int smem_tr    = 256 * 65 * 4;
    const int smem_gemm  = 65536;
    const int smem_fused = 196608 + 32768 + (256 + 256 + 32 + 32) * 4;  // 231,680

    cudaFuncSetAttribute(transpose_x_kernel,
                         cudaFuncAttributeMaxDynamicSharedMemorySize, smem_tr);
    cudaFuncSetAttribute(gemm_xg_kernel<DD>,
                         cudaFuncAttributeMaxDynamicSharedMemorySize, smem_gemm);
    cudaFuncSetAttribute(lstm_fused_kernel,
                         cudaFuncAttributeMaxDynamicSharedMemorySize, smem_fused);

    split_w_kernel<<<256, 256>>>(W_ih0, wih0hi, wih0lo, 4 * HH * DD);       // 1
    transpose_x_kernel<<<TT, NTH, smem_tr>>>(x);                            // 2
    dim3 ggrid(TTBB / 128, 16);
    gemm_xg_kernel<DD><<<ggrid, NTH, smem_gemm>>>(wih0hi, wih0lo, xhi, xlo, xg0);  // 3
    lstm_fused_kernel<<<NCTA, NTH, smem_fused>>>(W_hh0, b_ih0, b_hh0,
                                                 W_ih1, W_hh1, b_ih1, b_hh1,
                                                 xg0, out);                 // 4
    fc_kernel<<<BB, 128>>>(fc_w, fc_b, out);                                // 5
}